// round 1
// baseline (speedup 1.0000x reference)
#include <cuda_runtime.h>
#include <cuda_bf16.h>
#include <math.h>

// Problem constants
#define NN   50000
#define EE   800000
#define FDIM 128
#define HDIM 64
#define LL   3
#define GG   256
#define CC   10
#define TCOLS 384   // 2 views * 3 hops * 64

// ---------------- scratch (__device__ globals; no allocation allowed) ----------------
__device__ float g_T[(size_t)NN * TCOLS];     // per-layer GEMM output [N,384]
__device__ float g_h[(size_t)NN * FDIM];      // node features [N,128]
__device__ float g_u[(size_t)NN * HDIM];      // hop scratch [N,64]
__device__ float g_Wcat[FDIM * TCOLS];        // packed weights per layer

__device__ int   g_cnt[NN];
__device__ int   g_fill[NN];
__device__ int   g_rowptr[NN + 1];
__device__ int   g_csr_src[EE];
__device__ float g_csr_hom[EE];
__device__ float g_csr_het[EE];
__device__ float g_deg_hom[NN];
__device__ float g_deg_het[NN];
__device__ int   g_gptr[GG + 1];
__device__ float g_r[GG * 4 * HDIM];          // readout accumulator [G,256]

// ---------------- CSR build ----------------
__global__ void init_zero_kernel() {
    int i = blockIdx.x * blockDim.x + threadIdx.x;
    if (i < NN) {
        g_cnt[i] = 0;
        g_deg_hom[i] = 0.f;
        g_deg_het[i] = 0.f;
    }
}

__global__ void count_kernel(const int* __restrict__ ei,
                             const float* __restrict__ hm,
                             const float* __restrict__ tm) {
    int e = blockIdx.x * blockDim.x + threadIdx.x;
    if (e >= EE) return;
    int d = ei[EE + e];             // dst row of edge_index
    atomicAdd(&g_cnt[d], 1);
    atomicAdd(&g_deg_hom[d], hm[e]);
    atomicAdd(&g_deg_het[d], tm[e]);
}

__global__ void scan_kernel() {
    __shared__ int s[1024];
    const int t = threadIdx.x;
    const int CH = (NN + 1023) / 1024;
    int base = t * CH;
    int sum = 0;
    for (int i = 0; i < CH; i++) {
        int idx = base + i;
        if (idx < NN) sum += g_cnt[idx];
    }
    s[t] = sum;
    __syncthreads();
    for (int off = 1; off < 1024; off <<= 1) {
        int v = 0;
        if (t >= off) v = s[t - off];
        __syncthreads();
        if (t >= off) s[t] += v;
        __syncthreads();
    }
    int run = (t == 0) ? 0 : s[t - 1];
    for (int i = 0; i < CH; i++) {
        int idx = base + i;
        if (idx < NN) {
            int c = g_cnt[idx];
            g_rowptr[idx] = run;
            g_fill[idx] = run;
            run += c;
        }
    }
    if (t == 1023) g_rowptr[NN] = run;
}

__global__ void scatter_kernel(const int* __restrict__ ei,
                               const float* __restrict__ hm,
                               const float* __restrict__ tm) {
    int e = blockIdx.x * blockDim.x + threadIdx.x;
    if (e >= EE) return;
    int d = ei[EE + e];
    int p = atomicAdd(&g_fill[d], 1);
    g_csr_src[p] = ei[e];
    g_csr_hom[p] = hm[e];
    g_csr_het[p] = tm[e];
}

__global__ void gptr_kernel(const int* __restrict__ batch) {
    int n = blockIdx.x * blockDim.x + threadIdx.x;
    if (n >= NN) return;
    int b = batch[n];
    int prev = (n == 0) ? -1 : batch[n - 1];
    for (int g = prev + 1; g <= b; ++g) g_gptr[g] = n;
    if (n == NN - 1) {
        for (int g = b + 1; g <= GG; ++g) g_gptr[g] = NN;
    }
}

// ---------------- pack per-layer weights into [128,384] ----------------
__global__ void packW_kernel(const float* __restrict__ homW,
                             const float* __restrict__ hetW, int l) {
    int idx = blockIdx.x * blockDim.x + threadIdx.x;
    if (idx >= FDIM * TCOLS) return;
    int k = idx / TCOLS, c = idx % TCOLS;
    int v = c / 192;
    int j = (c % 192) / HDIM;
    int cc = c % HDIM;
    const float* Ws = v ? hetW : homW;
    g_Wcat[idx] = Ws[((size_t)(l * 3 + j) * FDIM + k) * HDIM + cc];
}

// ---------------- SGEMM: C[N,384] = A[N,128] @ Wcat[128,384] ----------------
#define BM 128
#define BN 128
#define BK 8
#define TM 8
#define TN 8
__global__ __launch_bounds__(256) void sgemm_kernel(const float* __restrict__ A,
                                                    float* __restrict__ C, int M) {
    const int K = FDIM, Nc = TCOLS;
    __shared__ float As[BK][BM];
    __shared__ float Bs[BK][BN];
    int tid = threadIdx.x;
    int rowBase = blockIdx.y * BM;
    int colBase = blockIdx.x * BN;

    int aRow = tid >> 1;
    int aCol = (tid & 1) * 4;
    int bRow = tid >> 5;
    int bCol = (tid & 31) * 4;

    float acc[TM][TN];
#pragma unroll
    for (int i = 0; i < TM; i++)
#pragma unroll
        for (int j = 0; j < TN; j++) acc[i][j] = 0.f;

    int tr = (tid / 16) * TM;
    int tc = (tid % 16) * TN;

    for (int k0 = 0; k0 < K; k0 += BK) {
        float4 av = make_float4(0.f, 0.f, 0.f, 0.f);
        int gr = rowBase + aRow;
        if (gr < M) av = *(const float4*)&A[(size_t)gr * K + k0 + aCol];
        As[aCol + 0][aRow] = av.x;
        As[aCol + 1][aRow] = av.y;
        As[aCol + 2][aRow] = av.z;
        As[aCol + 3][aRow] = av.w;

        float4 bv = *(const float4*)&g_Wcat[(size_t)(k0 + bRow) * Nc + colBase + bCol];
        *(float4*)&Bs[bRow][bCol] = bv;
        __syncthreads();

#pragma unroll
        for (int k = 0; k < BK; k++) {
            float ra[TM], rb[TN];
#pragma unroll
            for (int i = 0; i < TM; i++) ra[i] = As[k][tr + i];
#pragma unroll
            for (int j = 0; j < TN; j++) rb[j] = Bs[k][tc + j];
#pragma unroll
            for (int i = 0; i < TM; i++)
#pragma unroll
                for (int j = 0; j < TN; j++) acc[i][j] = fmaf(ra[i], rb[j], acc[i][j]);
        }
        __syncthreads();
    }

#pragma unroll
    for (int i = 0; i < TM; i++) {
        int gr = rowBase + tr + i;
        if (gr >= M) break;
#pragma unroll
        for (int j = 0; j < TN; j += 4) {
            *(float4*)&C[(size_t)gr * Nc + colBase + tc + j] =
                make_float4(acc[i][j], acc[i][j + 1], acc[i][j + 2], acc[i][j + 3]);
        }
    }
}

// (void)C unused suppression
// ---------------- aggregation: one warp per destination node ----------------
// out[n, outCol + c] = epi( (1/deg) * sum_e mask[e] * gatherSrc[src_e, srcCol + c] + addSrc[n, addCol + c] )
__global__ void agg_kernel(const float* __restrict__ gatherSrc, int srcLd, int srcCol,
                           const float* __restrict__ addSrc, int addLd, int addCol,
                           const float* __restrict__ mask,
                           const float* __restrict__ deg,
                           const float* __restrict__ bias,   // non-null => relu(. + bias)
                           float* __restrict__ out, int outLd, int outCol) {
    int gw = (blockIdx.x * blockDim.x + threadIdx.x) >> 5;
    int lane = threadIdx.x & 31;
    if (gw >= NN) return;
    int s = g_rowptr[gw];
    int e = g_rowptr[gw + 1];
    float ax = 0.f, ay = 0.f;
    for (int i = s; i < e; i++) {
        int sr = g_csr_src[i];
        float m = mask[i];
        float2 v = *(const float2*)&gatherSrc[(size_t)sr * srcLd + srcCol + 2 * lane];
        ax = fmaf(m, v.x, ax);
        ay = fmaf(m, v.y, ay);
    }
    float d = fmaxf(deg[gw], 1.f);
    float inv = 1.f / d;
    float2 a = *(const float2*)&addSrc[(size_t)gw * addLd + addCol + 2 * lane];
    float ox = fmaf(ax, inv, a.x);
    float oy = fmaf(ay, inv, a.y);
    if (bias) {
        ox = fmaxf(ox + bias[2 * lane], 0.f);
        oy = fmaxf(oy + bias[2 * lane + 1], 0.f);
    }
    float2 o = make_float2(ox, oy);
    *(float2*)&out[(size_t)gw * outLd + outCol + 2 * lane] = o;
}

// ---------------- readout: cat(max_pool, mean_pool) per graph ----------------
__global__ void readout_kernel(const float* __restrict__ h, int accumulate) {
    int g = blockIdx.x;
    int c = threadIdx.x;  // 128 threads = 2H features
    int s = g_gptr[g], e = g_gptr[g + 1];
    float mx = -INFINITY, sm = 0.f;
    for (int n = s; n < e; n++) {
        float v = h[(size_t)n * FDIM + c];
        mx = fmaxf(mx, v);
        sm += v;
    }
    float cnt = fmaxf((float)(e - s), 1.f);
    float mo = (e > s) ? mx : 0.f;
    float ao = sm / cnt;
    if (accumulate) {
        g_r[g * 256 + c] += mo;
        g_r[g * 256 + 128 + c] += ao;
    } else {
        g_r[g * 256 + c] = mo;
        g_r[g * 256 + 128 + c] = ao;
    }
}

// ---------------- MLP head + log_softmax ----------------
__global__ void mlp_kernel(const float* __restrict__ l1W, const float* __restrict__ l1b,
                           const float* __restrict__ l2W, const float* __restrict__ l2b,
                           const float* __restrict__ l3W, const float* __restrict__ l3b,
                           float* __restrict__ out) {
    int g = blockIdx.x;
    int t = threadIdx.x;  // 128 threads
    __shared__ float rs[256];
    __shared__ float z1[128];
    __shared__ float z2[64];
    __shared__ float lg[10];
    rs[t] = g_r[g * 256 + t];
    rs[t + 128] = g_r[g * 256 + 128 + t];
    __syncthreads();
    float acc = l1b[t];
#pragma unroll 8
    for (int k = 0; k < 256; k++) acc = fmaf(rs[k], l1W[k * 128 + t], acc);
    z1[t] = fmaxf(acc, 0.f);
    __syncthreads();
    if (t < 64) {
        float a = l2b[t];
#pragma unroll 8
        for (int k = 0; k < 128; k++) a = fmaf(z1[k], l2W[k * 64 + t], a);
        z2[t] = fmaxf(a, 0.f);
    }
    __syncthreads();
    if (t < 10) {
        float a = l3b[t];
#pragma unroll 8
        for (int k = 0; k < 64; k++) a = fmaf(z2[k], l3W[k * 10 + t], a);
        lg[t] = a;
    }
    __syncthreads();
    if (t == 0) {
        float mx = lg[0];
        for (int i = 1; i < CC; i++) mx = fmaxf(mx, lg[i]);
        float se = 0.f;
        for (int i = 0; i < CC; i++) se += expf(lg[i] - mx);
        float lse = mx + logf(se);
        for (int i = 0; i < CC; i++) out[g * CC + i] = lg[i] - lse;
    }
}

// ---------------- driver ----------------
extern "C" void kernel_launch(void* const* d_in, const int* in_sizes, int n_in,
                              void* d_out, int out_size) {
    const float* x       = (const float*)d_in[0];
    const int*   ei      = (const int*)d_in[1];
    const int*   batch   = (const int*)d_in[2];
    const float* hom_m   = (const float*)d_in[3];
    const float* het_m   = (const float*)d_in[4];
    const float* hom_W   = (const float*)d_in[5];
    const float* hom_b   = (const float*)d_in[6];
    const float* het_W   = (const float*)d_in[7];
    const float* het_b   = (const float*)d_in[8];
    const float* l1W     = (const float*)d_in[9];
    const float* l1b     = (const float*)d_in[10];
    const float* l2W     = (const float*)d_in[11];
    const float* l2b     = (const float*)d_in[12];
    const float* l3W     = (const float*)d_in[13];
    const float* l3b     = (const float*)d_in[14];
    float* out = (float*)d_out;
    (void)in_sizes; (void)n_in; (void)out_size;

    // device-global pointers for kernel args
    float *T_p, *h_p, *u_p, *dh_p, *dt_p, *chm_p, *cht_p;
    cudaGetSymbolAddress((void**)&T_p,  g_T);
    cudaGetSymbolAddress((void**)&h_p,  g_h);
    cudaGetSymbolAddress((void**)&u_p,  g_u);
    cudaGetSymbolAddress((void**)&dh_p, g_deg_hom);
    cudaGetSymbolAddress((void**)&dt_p, g_deg_het);
    cudaGetSymbolAddress((void**)&chm_p, g_csr_hom);
    cudaGetSymbolAddress((void**)&cht_p, g_csr_het);

    // ---- CSR build (per call; cheap) ----
    init_zero_kernel<<<(NN + 255) / 256, 256>>>();
    count_kernel<<<(EE + 255) / 256, 256>>>(ei, hom_m, het_m);
    scan_kernel<<<1, 1024>>>();
    gptr_kernel<<<(NN + 255) / 256, 256>>>(batch);
    scatter_kernel<<<(EE + 255) / 256, 256>>>(ei, hom_m, het_m);

    const int aggBlocks = (NN * 32 + 255) / 256;
    dim3 gemmGrid(TCOLS / BN, (NN + BM - 1) / BM);

    for (int l = 0; l < LL; l++) {
        packW_kernel<<<(FDIM * TCOLS + 255) / 256, 256>>>(hom_W, het_W, l);
        const float* hin = (l == 0) ? x : h_p;
        sgemm_kernel<<<gemmGrid, 256>>>(hin, T_p, NN);

        for (int v = 0; v < 2; v++) {
            const float* mask = v ? cht_p : chm_p;
            const float* deg  = v ? dt_p  : dh_p;
            const float* bias = (v ? het_b : hom_b) + l * HDIM;
            int cb = v * 192;
            // hop1: u = A*(h W2) + (h W1)
            agg_kernel<<<aggBlocks, 256>>>(T_p, TCOLS, cb + 128,
                                           T_p, TCOLS, cb + 64,
                                           mask, deg, nullptr,
                                           u_p, HDIM, 0);
            // hop2: h[:, v*64:] = relu( A*u + (h W0) + b )
            agg_kernel<<<aggBlocks, 256>>>(u_p, HDIM, 0,
                                           T_p, TCOLS, cb,
                                           mask, deg, bias,
                                           h_p, FDIM, v * HDIM);
        }
        if (l >= 1) readout_kernel<<<GG, FDIM>>>(h_p, (l == 1) ? 0 : 1);
    }

    mlp_kernel<<<GG, 128>>>(l1W, l1b, l2W, l2b, l3W, l3b, out);
}

// round 2
// speedup vs baseline: 1.0835x; 1.0835x over previous
#include <cuda_runtime.h>
#include <cuda_bf16.h>
#include <math.h>

// Problem constants
#define NN   50000
#define EE   800000
#define FDIM 128
#define HDIM 64
#define LL   3
#define GG   256
#define CC   10
#define TCOLS 384   // 6 blocks of 64: [W2hom|W2het|W1hom|W1het|W0hom|W0het]

// ---------------- scratch (__device__ globals; no allocation allowed) ----------------
__device__ float g_T[(size_t)NN * TCOLS];     // per-layer GEMM output [N,384]
__device__ float g_h[(size_t)NN * FDIM];      // node features [N,128] (hom|het)
__device__ float g_u[(size_t)NN * FDIM];      // hop scratch [N,128] (hom|het)
__device__ float g_Wcat[FDIM * TCOLS];        // packed weights per layer

__device__ int    g_cnt[NN];
__device__ int    g_fill[NN];
__device__ int    g_rowptr[NN + 1];
__device__ int    g_csr_src[EE];
__device__ float2 g_csr_mask[EE];             // (hom, het)
__device__ float  g_deg_hom[NN];
__device__ float  g_deg_het[NN];
__device__ int    g_gptr[GG + 1];
__device__ float  g_r[GG * 4 * HDIM];         // readout accumulator [G,256]

// ---------------- CSR build ----------------
__global__ void init_zero_kernel() {
    int i = blockIdx.x * blockDim.x + threadIdx.x;
    if (i < NN) {
        g_cnt[i] = 0;
        g_deg_hom[i] = 0.f;
        g_deg_het[i] = 0.f;
    }
}

__global__ void count_kernel(const int* __restrict__ ei,
                             const float* __restrict__ hm,
                             const float* __restrict__ tm) {
    int e = blockIdx.x * blockDim.x + threadIdx.x;
    if (e >= EE) return;
    int d = ei[EE + e];             // dst row of edge_index
    atomicAdd(&g_cnt[d], 1);
    atomicAdd(&g_deg_hom[d], hm[e]);
    atomicAdd(&g_deg_het[d], tm[e]);
}

__global__ void scan_kernel() {
    __shared__ int s[1024];
    const int t = threadIdx.x;
    const int CH = (NN + 1023) / 1024;
    int base = t * CH;
    int sum = 0;
    for (int i = 0; i < CH; i++) {
        int idx = base + i;
        if (idx < NN) sum += g_cnt[idx];
    }
    s[t] = sum;
    __syncthreads();
    for (int off = 1; off < 1024; off <<= 1) {
        int v = 0;
        if (t >= off) v = s[t - off];
        __syncthreads();
        if (t >= off) s[t] += v;
        __syncthreads();
    }
    int run = (t == 0) ? 0 : s[t - 1];
    for (int i = 0; i < CH; i++) {
        int idx = base + i;
        if (idx < NN) {
            int c = g_cnt[idx];
            g_rowptr[idx] = run;
            g_fill[idx] = run;
            run += c;
        }
    }
    if (t == 1023) g_rowptr[NN] = run;
}

__global__ void scatter_kernel(const int* __restrict__ ei,
                               const float* __restrict__ hm,
                               const float* __restrict__ tm) {
    int e = blockIdx.x * blockDim.x + threadIdx.x;
    if (e >= EE) return;
    int d = ei[EE + e];
    int p = atomicAdd(&g_fill[d], 1);
    g_csr_src[p] = ei[e];
    g_csr_mask[p] = make_float2(hm[e], tm[e]);
}

__global__ void gptr_kernel(const int* __restrict__ batch) {
    int n = blockIdx.x * blockDim.x + threadIdx.x;
    if (n >= NN) return;
    int b = batch[n];
    int prev = (n == 0) ? -1 : batch[n - 1];
    for (int g = prev + 1; g <= b; ++g) g_gptr[g] = n;
    if (n == NN - 1) {
        for (int g = b + 1; g <= GG; ++g) g_gptr[g] = NN;
    }
}

// ---------------- pack per-layer weights into [128,384] ----------------
// column block b (of 6 x 64): view = b&1 (0 hom), hop j = 2 - b/2
__global__ void packW_kernel(const float* __restrict__ homW,
                             const float* __restrict__ hetW, int l) {
    int idx = blockIdx.x * blockDim.x + threadIdx.x;
    if (idx >= FDIM * TCOLS) return;
    int k = idx / TCOLS, c = idx % TCOLS;
    int b = c / HDIM;
    int v = b & 1;
    int j = 2 - (b >> 1);
    int cc = c % HDIM;
    const float* Ws = v ? hetW : homW;
    g_Wcat[idx] = Ws[((size_t)(l * 3 + j) * FDIM + k) * HDIM + cc];
}

// ---------------- SGEMM: C[N,384] = A[N,128] @ Wcat[128,384] ----------------
#define BM 128
#define BN 128
#define BK 16
#define TM 8
#define TN 8
__global__ __launch_bounds__(256) void sgemm_kernel(const float* __restrict__ A,
                                                    float* __restrict__ C, int M) {
    const int K = FDIM, Nc = TCOLS;
    __shared__ float As[BK][BM];
    __shared__ float Bs[BK][BN];
    int tid = threadIdx.x;
    int rowBase = blockIdx.y * BM;
    int colBase = blockIdx.x * BN;

    int aRow = tid >> 1;
    int aCol = (tid & 1) * 8;
    int bRow = tid >> 4;
    int bCol = (tid & 15) * 8;

    float acc[TM][TN];
#pragma unroll
    for (int i = 0; i < TM; i++)
#pragma unroll
        for (int j = 0; j < TN; j++) acc[i][j] = 0.f;

    int tr = (tid / 16) * TM;
    int tc = (tid % 16) * TN;

    for (int k0 = 0; k0 < K; k0 += BK) {
        float4 av0 = make_float4(0.f, 0.f, 0.f, 0.f);
        float4 av1 = make_float4(0.f, 0.f, 0.f, 0.f);
        int gr = rowBase + aRow;
        if (gr < M) {
            av0 = *(const float4*)&A[(size_t)gr * K + k0 + aCol];
            av1 = *(const float4*)&A[(size_t)gr * K + k0 + aCol + 4];
        }
        As[aCol + 0][aRow] = av0.x;
        As[aCol + 1][aRow] = av0.y;
        As[aCol + 2][aRow] = av0.z;
        As[aCol + 3][aRow] = av0.w;
        As[aCol + 4][aRow] = av1.x;
        As[aCol + 5][aRow] = av1.y;
        As[aCol + 6][aRow] = av1.z;
        As[aCol + 7][aRow] = av1.w;

        float4 bv0 = *(const float4*)&g_Wcat[(size_t)(k0 + bRow) * Nc + colBase + bCol];
        float4 bv1 = *(const float4*)&g_Wcat[(size_t)(k0 + bRow) * Nc + colBase + bCol + 4];
        *(float4*)&Bs[bRow][bCol] = bv0;
        *(float4*)&Bs[bRow][bCol + 4] = bv1;
        __syncthreads();

#pragma unroll
        for (int k = 0; k < BK; k++) {
            float ra[TM], rb[TN];
#pragma unroll
            for (int i = 0; i < TM; i++) ra[i] = As[k][tr + i];
#pragma unroll
            for (int j = 0; j < TN; j++) rb[j] = Bs[k][tc + j];
#pragma unroll
            for (int i = 0; i < TM; i++)
#pragma unroll
                for (int j = 0; j < TN; j++) acc[i][j] = fmaf(ra[i], rb[j], acc[i][j]);
        }
        __syncthreads();
    }

#pragma unroll
    for (int i = 0; i < TM; i++) {
        int gr = rowBase + tr + i;
        if (gr >= M) break;
#pragma unroll
        for (int j = 0; j < TN; j += 4) {
            *(float4*)&C[(size_t)gr * Nc + colBase + tc + j] =
                make_float4(acc[i][j], acc[i][j + 1], acc[i][j + 2], acc[i][j + 3]);
        }
    }
}

// ---------------- fused two-view aggregation: one warp per destination node ----------------
// out[n, 0:128] = epi( (1/deg_view) * sum_e mask_view[e] * gather[src_e, 0:128] + add[n, acol:acol+128] )
// cols 0:64 = hom view, 64:128 = het view. Lane handles 4 cols (float4).
__global__ void agg2_kernel(const float* __restrict__ gather, int gld,
                            const float* __restrict__ add, int ald, int acol,
                            const float* __restrict__ hom_b,  // non-null => relu(.+bias)
                            const float* __restrict__ het_b,
                            float* __restrict__ out) {
    int gw = (blockIdx.x * blockDim.x + threadIdx.x) >> 5;
    int lane = threadIdx.x & 31;
    if (gw >= NN) return;
    const bool het = lane >= 16;
    int s = g_rowptr[gw];
    int e = g_rowptr[gw + 1];
    float ax = 0.f, ay = 0.f, az = 0.f, aw = 0.f;
    for (int i = s; i < e; i++) {
        int sr = g_csr_src[i];
        float2 mm = g_csr_mask[i];
        float m = het ? mm.y : mm.x;
        float4 v = *(const float4*)&gather[(size_t)sr * gld + 4 * lane];
        ax = fmaf(m, v.x, ax);
        ay = fmaf(m, v.y, ay);
        az = fmaf(m, v.z, az);
        aw = fmaf(m, v.w, aw);
    }
    float d = fmaxf(het ? g_deg_het[gw] : g_deg_hom[gw], 1.f);
    float inv = 1.f / d;
    float4 a = *(const float4*)&add[(size_t)gw * ald + acol + 4 * lane];
    float ox = fmaf(ax, inv, a.x);
    float oy = fmaf(ay, inv, a.y);
    float oz = fmaf(az, inv, a.z);
    float ow = fmaf(aw, inv, a.w);
    if (hom_b) {
        const float* bb = het ? het_b : hom_b;
        int bi = 4 * lane - (het ? 64 : 0);
        ox = fmaxf(ox + bb[bi + 0], 0.f);
        oy = fmaxf(oy + bb[bi + 1], 0.f);
        oz = fmaxf(oz + bb[bi + 2], 0.f);
        ow = fmaxf(ow + bb[bi + 3], 0.f);
    }
    *(float4*)&out[(size_t)gw * FDIM + 4 * lane] = make_float4(ox, oy, oz, ow);
}

// ---------------- readout: cat(max_pool, mean_pool) per graph ----------------
__global__ void readout_kernel(const float* __restrict__ h, int accumulate) {
    int g = blockIdx.x;
    int c = threadIdx.x;  // 128 threads = 2H features
    int s = g_gptr[g], e = g_gptr[g + 1];
    float mx = -INFINITY, sm = 0.f;
    for (int n = s; n < e; n++) {
        float v = h[(size_t)n * FDIM + c];
        mx = fmaxf(mx, v);
        sm += v;
    }
    float cnt = fmaxf((float)(e - s), 1.f);
    float mo = (e > s) ? mx : 0.f;
    float ao = sm / cnt;
    if (accumulate) {
        g_r[g * 256 + c] += mo;
        g_r[g * 256 + 128 + c] += ao;
    } else {
        g_r[g * 256 + c] = mo;
        g_r[g * 256 + 128 + c] = ao;
    }
}

// ---------------- MLP head + log_softmax ----------------
__global__ void mlp_kernel(const float* __restrict__ l1W, const float* __restrict__ l1b,
                           const float* __restrict__ l2W, const float* __restrict__ l2b,
                           const float* __restrict__ l3W, const float* __restrict__ l3b,
                           float* __restrict__ out) {
    int g = blockIdx.x;
    int t = threadIdx.x;  // 128 threads
    __shared__ float rs[256];
    __shared__ float z1[128];
    __shared__ float z2[64];
    __shared__ float lg[10];
    rs[t] = g_r[g * 256 + t];
    rs[t + 128] = g_r[g * 256 + 128 + t];
    __syncthreads();
    float acc = l1b[t];
#pragma unroll 8
    for (int k = 0; k < 256; k++) acc = fmaf(rs[k], l1W[k * 128 + t], acc);
    z1[t] = fmaxf(acc, 0.f);
    __syncthreads();
    if (t < 64) {
        float a = l2b[t];
#pragma unroll 8
        for (int k = 0; k < 128; k++) a = fmaf(z1[k], l2W[k * 64 + t], a);
        z2[t] = fmaxf(a, 0.f);
    }
    __syncthreads();
    if (t < 10) {
        float a = l3b[t];
#pragma unroll 8
        for (int k = 0; k < 64; k++) a = fmaf(z2[k], l3W[k * 10 + t], a);
        lg[t] = a;
    }
    __syncthreads();
    if (t == 0) {
        float mx = lg[0];
        for (int i = 1; i < CC; i++) mx = fmaxf(mx, lg[i]);
        float se = 0.f;
        for (int i = 0; i < CC; i++) se += expf(lg[i] - mx);
        float lse = mx + logf(se);
        for (int i = 0; i < CC; i++) out[g * CC + i] = lg[i] - lse;
    }
}

// ---------------- driver ----------------
extern "C" void kernel_launch(void* const* d_in, const int* in_sizes, int n_in,
                              void* d_out, int out_size) {
    const float* x       = (const float*)d_in[0];
    const int*   ei      = (const int*)d_in[1];
    const int*   batch   = (const int*)d_in[2];
    const float* hom_m   = (const float*)d_in[3];
    const float* het_m   = (const float*)d_in[4];
    const float* hom_W   = (const float*)d_in[5];
    const float* hom_b   = (const float*)d_in[6];
    const float* het_W   = (const float*)d_in[7];
    const float* het_b   = (const float*)d_in[8];
    const float* l1W     = (const float*)d_in[9];
    const float* l1b     = (const float*)d_in[10];
    const float* l2W     = (const float*)d_in[11];
    const float* l2b     = (const float*)d_in[12];
    const float* l3W     = (const float*)d_in[13];
    const float* l3b     = (const float*)d_in[14];
    float* out = (float*)d_out;
    (void)in_sizes; (void)n_in; (void)out_size;

    float *T_p, *h_p, *u_p;
    cudaGetSymbolAddress((void**)&T_p, g_T);
    cudaGetSymbolAddress((void**)&h_p, g_h);
    cudaGetSymbolAddress((void**)&u_p, g_u);

    // ---- CSR build (per call; cheap) ----
    init_zero_kernel<<<(NN + 255) / 256, 256>>>();
    count_kernel<<<(EE + 255) / 256, 256>>>(ei, hom_m, het_m);
    scan_kernel<<<1, 1024>>>();
    gptr_kernel<<<(NN + 255) / 256, 256>>>(batch);
    scatter_kernel<<<(EE + 255) / 256, 256>>>(ei, hom_m, het_m);

    const int aggBlocks = (NN * 32 + 255) / 256;
    dim3 gemmGrid(TCOLS / BN, (NN + BM - 1) / BM);

    for (int l = 0; l < LL; l++) {
        packW_kernel<<<(FDIM * TCOLS + 255) / 256, 256>>>(hom_W, het_W, l);
        const float* hin = (l == 0) ? x : h_p;
        sgemm_kernel<<<gemmGrid, 256>>>(hin, T_p, NN);

        // hop1 (both views fused): u = A*(h W2) + (h W1)     [gather T cols 0:128, add T cols 128:256]
        agg2_kernel<<<aggBlocks, 256>>>(T_p, TCOLS,
                                        T_p, TCOLS, 128,
                                        nullptr, nullptr,
                                        u_p);
        // hop2 (both views fused): h = relu( A*u + (h W0) + b )   [gather u, add T cols 256:384]
        agg2_kernel<<<aggBlocks, 256>>>(u_p, FDIM,
                                        T_p, TCOLS, 256,
                                        hom_b + l * HDIM, het_b + l * HDIM,
                                        h_p);

        if (l >= 1) readout_kernel<<<GG, FDIM>>>(h_p, (l == 1) ? 0 : 1);
    }

    mlp_kernel<<<GG, 128>>>(l1W, l1b, l2W, l2b, l3W, l3b, out);
}